// round 3
// baseline (speedup 1.0000x reference)
#include <cuda_runtime.h>
#include <cstdint>

// ---------------------------------------------------------------------------
// Problem constants (fixed by the dataset): N=10000, E=320000, H=2, F=128
// ---------------------------------------------------------------------------
#define NMAX 10016
#define EMAX 320032

// Scratch (static device globals — no allocation APIs allowed)
__device__ float g_h[NMAX * 256];       // x @ W_gat^T   [N,256] (head-major)
__device__ float g_as[NMAX * 2];        // a_src per node, per head
__device__ float g_ad[NMAX * 2];        // a_dst per node, per head
__device__ int   g_deg[NMAX];
__device__ int   g_cur[NMAX];
__device__ int   g_off[NMAX + 1];
__device__ int   g_ssrc[EMAX];          // src ids sorted by dst
__device__ float g_gact[NMAX * 256];    // lrelu(GAT out + b_gat)
__device__ float g_hA[NMAX * 128];
__device__ float g_hB[NMAX * 64];
__device__ float g_hC[NMAX * 32];
__device__ float g_h3[NMAX * 3];
__device__ float g_sq[NMAX];

__device__ __forceinline__ float lrelu(float x, float s) {
    return x >= 0.f ? x : s * x;
}

// ---------------------------------------------------------------------------
// Counting sort of edges by dst
// ---------------------------------------------------------------------------
__global__ void init_kernel(int n) {
    int i = blockIdx.x * blockDim.x + threadIdx.x;
    if (i < n) { g_deg[i] = 0; g_cur[i] = 0; }
}

__global__ void hist_kernel(const int* __restrict__ ei, int E) {
    int e = blockIdx.x * blockDim.x + threadIdx.x;
    if (e < E) atomicAdd(&g_deg[ei[E + e]], 1);
}

// single-block scan over n (<= 16384) degree counts -> exclusive offsets
__global__ void scan_kernel(int n) {
    __shared__ int ssum[1024];
    int t = threadIdx.x;
    const int CH = (n + 1023) >> 10;   // elems per thread (10 for n=10000)
    int vals[16];
    int base = t * CH;
    int loc = 0;
    for (int i = 0; i < CH; i++) {
        int idx = base + i;
        int v = (idx < n) ? g_deg[idx] : 0;
        vals[i] = v;
        loc += v;
    }
    ssum[t] = loc;
    __syncthreads();
    for (int d = 1; d < 1024; d <<= 1) {
        int add = (t >= d) ? ssum[t - d] : 0;
        __syncthreads();
        ssum[t] += add;
        __syncthreads();
    }
    int run = (t == 0) ? 0 : ssum[t - 1];
    for (int i = 0; i < CH; i++) {
        int idx = base + i;
        if (idx < n) g_off[idx] = run;
        run += vals[i];
    }
    if (t == 1023) g_off[n] = ssum[1023];
}

__global__ void scatter_kernel(const int* __restrict__ ei, int E) {
    int e = blockIdx.x * blockDim.x + threadIdx.x;
    if (e < E) {
        int dst = ei[E + e];
        int pos = g_off[dst] + atomicAdd(&g_cur[dst], 1);
        g_ssrc[pos] = ei[e];
    }
}

// ---------------------------------------------------------------------------
// GAT GEMM: g_h[m,n] = sum_k x[m,k] * W_gat[n,k]
// BM=128, BN=64, BK=16, 256 threads, 8x4 microtile.
// 3 LDS.128 per 32 FFMA per k-step per thread.
// ---------------------------------------------------------------------------
__global__ void gemm_gat_kernel(const float* __restrict__ A,
                                const float* __restrict__ B, int M) {
    const int K = 256, Nmat = 256;
    __shared__ float As[16][132];
    __shared__ float Bs[16][68];
    int tid = threadIdx.x;
    int tx = tid & 15, ty = tid >> 4;      // 16 x 16 thread grid
    int rowBase = blockIdx.y * 128;
    int colBase = blockIdx.x * 64;
    float acc[8][4] = {};
    for (int kk = 0; kk < K; kk += 16) {
        #pragma unroll
        for (int i = 0; i < 8; i++) {       // 128*16/256 = 8 loads
            int l = tid + i * 256;
            int m = l >> 4, k = l & 15;
            int gr = rowBase + m;
            As[k][m] = (gr < M) ? A[(size_t)gr * K + kk + k] : 0.f;
        }
        #pragma unroll
        for (int i = 0; i < 4; i++) {       // 64*16/256 = 4 loads
            int l = tid + i * 256;
            int nn = l >> 4, k = l & 15;
            Bs[k][nn] = B[(size_t)(colBase + nn) * K + kk + k];
        }
        __syncthreads();
        #pragma unroll
        for (int k = 0; k < 16; k++) {
            float4 a0 = *(const float4*)&As[k][ty * 8];
            float4 a1 = *(const float4*)&As[k][ty * 8 + 4];
            float4 b4 = *(const float4*)&Bs[k][tx * 4];
            float av[8] = {a0.x, a0.y, a0.z, a0.w, a1.x, a1.y, a1.z, a1.w};
            float bv[4] = {b4.x, b4.y, b4.z, b4.w};
            #pragma unroll
            for (int i = 0; i < 8; i++)
                #pragma unroll
                for (int j = 0; j < 4; j++)
                    acc[i][j] = fmaf(av[i], bv[j], acc[i][j]);
        }
        __syncthreads();
    }
    #pragma unroll
    for (int i = 0; i < 8; i++) {
        int gr = rowBase + ty * 8 + i;
        if (gr < M) {
            int gc = colBase + tx * 4;
            *(float4*)&g_h[(size_t)gr * Nmat + gc] =
                make_float4(acc[i][0], acc[i][1], acc[i][2], acc[i][3]);
        }
    }
}

// ---------------------------------------------------------------------------
// a_src / a_dst: one warp per node
// ---------------------------------------------------------------------------
__global__ void attn_kernel(const float* __restrict__ att_src,
                            const float* __restrict__ att_dst, int n) {
    int gw = (blockIdx.x * blockDim.x + threadIdx.x) >> 5;
    if (gw >= n) return;
    int lane = threadIdx.x & 31;
    const float* hr = g_h + (size_t)gw * 256;
    float s0 = 0, s1 = 0, d0 = 0, d1 = 0;
    #pragma unroll
    for (int j = 0; j < 8; j++) {
        int f = lane + 32 * j;
        float v = hr[f];
        float as = att_src[f], ad = att_dst[f];
        if (j < 4) { s0 = fmaf(v, as, s0); d0 = fmaf(v, ad, d0); }
        else       { s1 = fmaf(v, as, s1); d1 = fmaf(v, ad, d1); }
    }
    #pragma unroll
    for (int o = 16; o; o >>= 1) {
        s0 += __shfl_xor_sync(0xffffffffu, s0, o);
        s1 += __shfl_xor_sync(0xffffffffu, s1, o);
        d0 += __shfl_xor_sync(0xffffffffu, d0, o);
        d1 += __shfl_xor_sync(0xffffffffu, d1, o);
    }
    if (lane == 0) {
        g_as[2 * gw] = s0; g_as[2 * gw + 1] = s1;
        g_ad[2 * gw] = d0; g_ad[2 * gw + 1] = d1;
    }
}

// ---------------------------------------------------------------------------
// GAT aggregation: one block per dst node. Two passes (max; exp-sum + weighted
// accumulate), normalize at end. Self-loop handled explicitly.
// ---------------------------------------------------------------------------
__global__ void gat_aggregate_kernel(const float* __restrict__ b_gat, int n) {
    int dst = blockIdx.x;
    if (dst >= n) return;
    int tid = threadIdx.x, lane = tid & 31, w = tid >> 5;
    __shared__ float smax[8][2];
    __shared__ float ssum[8][2];
    __shared__ float sm[2];
    __shared__ float accbuf[8][256];

    int beg = g_off[dst], end = g_off[dst + 1];
    float2 adv = ((const float2*)g_ad)[dst];
    float ad0 = adv.x, ad1 = adv.y;
    float2 asd = ((const float2*)g_as)[dst];
    float es0 = lrelu(asd.x + ad0, 0.2f);
    float es1 = lrelu(asd.y + ad1, 0.2f);

    // pass 1: segment max (includes self loop)
    float m0 = es0, m1 = es1;
    for (int p = beg + tid; p < end; p += 256) {
        int s = g_ssrc[p];
        float2 av = ((const float2*)g_as)[s];
        m0 = fmaxf(m0, lrelu(av.x + ad0, 0.2f));
        m1 = fmaxf(m1, lrelu(av.y + ad1, 0.2f));
    }
    #pragma unroll
    for (int o = 16; o; o >>= 1) {
        m0 = fmaxf(m0, __shfl_xor_sync(0xffffffffu, m0, o));
        m1 = fmaxf(m1, __shfl_xor_sync(0xffffffffu, m1, o));
    }
    if (lane == 0) { smax[w][0] = m0; smax[w][1] = m1; }
    __syncthreads();
    if (tid == 0) {
        float a = smax[0][0], b = smax[0][1];
        #pragma unroll
        for (int q = 1; q < 8; q++) { a = fmaxf(a, smax[q][0]); b = fmaxf(b, smax[q][1]); }
        sm[0] = a; sm[1] = b;
    }
    __syncthreads();
    m0 = sm[0]; m1 = sm[1];

    // pass 2: exp-sum + weighted accumulate; edges distributed across warps
    float acc[8] = {0, 0, 0, 0, 0, 0, 0, 0};
    float s0 = 0, s1 = 0;
    for (int p = beg + w; p < end; p += 8) {
        int s = g_ssrc[p];
        float2 av = ((const float2*)g_as)[s];
        float ex0 = __expf(lrelu(av.x + ad0, 0.2f) - m0);
        float ex1 = __expf(lrelu(av.y + ad1, 0.2f) - m1);
        s0 += ex0; s1 += ex1;
        const float* hs = g_h + (size_t)s * 256;
        #pragma unroll
        for (int j = 0; j < 8; j++)
            acc[j] = fmaf(hs[j * 32 + lane], (j < 4 ? ex0 : ex1), acc[j]);
    }
    if (w == 0) {  // self loop
        float ex0 = __expf(es0 - m0), ex1 = __expf(es1 - m1);
        s0 += ex0; s1 += ex1;
        const float* hs = g_h + (size_t)dst * 256;
        #pragma unroll
        for (int j = 0; j < 8; j++)
            acc[j] = fmaf(hs[j * 32 + lane], (j < 4 ? ex0 : ex1), acc[j]);
    }
    if (lane == 0) { ssum[w][0] = s0; ssum[w][1] = s1; }
    #pragma unroll
    for (int j = 0; j < 8; j++) accbuf[w][j * 32 + lane] = acc[j];
    __syncthreads();

    float t0 = 0, t1 = 0;
    #pragma unroll
    for (int q = 0; q < 8; q++) { t0 += ssum[q][0]; t1 += ssum[q][1]; }
    float inv0 = 1.f / (t0 + 1e-16f);
    float inv1 = 1.f / (t1 + 1e-16f);
    float v = 0;
    #pragma unroll
    for (int q = 0; q < 8; q++) v += accbuf[q][tid];
    v = v * (tid < 128 ? inv0 : inv1) + b_gat[tid];
    g_gact[(size_t)dst * 256 + tid] = lrelu(v, 0.01f);
}

// ---------------------------------------------------------------------------
// Fused GEMM + bias + LayerNorm + LeakyReLU(0.01).
// One block computes BM rows x full NOUT output width.
// ---------------------------------------------------------------------------
template <int K, int NOUT, int BM>
__device__ __forceinline__ void mlp_ln_body(const float* __restrict__ A,
                                            const float* __restrict__ W,
                                            const float* __restrict__ bias,
                                            const float* __restrict__ lnw,
                                            const float* __restrict__ lnb,
                                            float* __restrict__ out, int M) {
    constexpr int TX = NOUT / 4;
    constexpr int TY = BM / 4;
    static_assert(TX * TY == 256, "thread grid must be 256");
    __shared__ float As[16][BM + 4];
    __shared__ float Bs[16][NOUT + 4];
    __shared__ float Cs[BM][NOUT];
    int tid = threadIdx.x;
    int tx = tid % TX, ty = tid / TX;
    int rowBase = blockIdx.x * BM;
    float acc[4][4] = {};
    for (int kk = 0; kk < K; kk += 16) {
        #pragma unroll
        for (int i = 0; i < (BM * 16) / 256; i++) {
            int l = tid + i * 256;
            int m = l >> 4, k = l & 15;
            int gr = rowBase + m;
            As[k][m] = (gr < M) ? A[(size_t)gr * K + kk + k] : 0.f;
        }
        #pragma unroll
        for (int i = 0; i < (NOUT * 16) / 256; i++) {
            int l = tid + i * 256;
            int nn = l >> 4, k = l & 15;
            Bs[k][nn] = W[nn * K + kk + k];
        }
        __syncthreads();
        #pragma unroll
        for (int k = 0; k < 16; k++) {
            float4 a4 = *(const float4*)&As[k][ty * 4];
            float4 b4 = *(const float4*)&Bs[k][tx * 4];
            float av[4] = {a4.x, a4.y, a4.z, a4.w};
            float bv[4] = {b4.x, b4.y, b4.z, b4.w};
            #pragma unroll
            for (int i = 0; i < 4; i++)
                #pragma unroll
                for (int j = 0; j < 4; j++)
                    acc[i][j] = fmaf(av[i], bv[j], acc[i][j]);
        }
        __syncthreads();
    }
    // bias add + stash to shared for row-wise LN
    float4 bb = *(const float4*)&bias[tx * 4];
    #pragma unroll
    for (int i = 0; i < 4; i++) {
        *(float4*)&Cs[ty * 4 + i][tx * 4] =
            make_float4(acc[i][0] + bb.x, acc[i][1] + bb.y,
                        acc[i][2] + bb.z, acc[i][3] + bb.w);
    }
    __syncthreads();
    // LayerNorm + LeakyReLU, one warp handles BM/8 rows
    constexpr int RPW = BM / 8;
    constexpr int VPL = NOUT / 32;
    int w = tid >> 5, lane = tid & 31;
    for (int rr = 0; rr < RPW; rr++) {
        int r = w * RPW + rr;
        float v[VPL];
        float s = 0, s2 = 0;
        #pragma unroll
        for (int vi = 0; vi < VPL; vi++) {
            v[vi] = Cs[r][lane + vi * 32];
            s += v[vi];
            s2 = fmaf(v[vi], v[vi], s2);
        }
        #pragma unroll
        for (int o = 16; o; o >>= 1) {
            s  += __shfl_xor_sync(0xffffffffu, s, o);
            s2 += __shfl_xor_sync(0xffffffffu, s2, o);
        }
        float mean = s * (1.f / NOUT);
        float var = fmaxf(s2 * (1.f / NOUT) - mean * mean, 0.f);
        float rstd = rsqrtf(var + 1e-5f);
        int gr = rowBase + r;
        if (gr < M) {
            #pragma unroll
            for (int vi = 0; vi < VPL; vi++) {
                int c = lane + vi * 32;
                float o2 = (v[vi] - mean) * rstd * lnw[c] + lnb[c];
                out[(size_t)gr * NOUT + c] = o2 >= 0.f ? o2 : 0.01f * o2;
            }
        }
    }
}

__global__ void mlp_a_kernel(const float* __restrict__ W, const float* __restrict__ bias,
                             const float* __restrict__ lnw, const float* __restrict__ lnb, int M) {
    mlp_ln_body<256, 128, 32>(g_gact, W, bias, lnw, lnb, g_hA, M);
}
__global__ void mlp_1_kernel(const float* __restrict__ W, const float* __restrict__ bias,
                             const float* __restrict__ lnw, const float* __restrict__ lnb, int M) {
    mlp_ln_body<128, 64, 64>(g_hA, W, bias, lnw, lnb, g_hB, M);
}
__global__ void mlp_2_kernel(const float* __restrict__ W, const float* __restrict__ bias,
                             const float* __restrict__ lnw, const float* __restrict__ lnb, int M) {
    mlp_ln_body<64, 32, 128>(g_hB, W, bias, lnw, lnb, g_hC, M);
}

// ---------------------------------------------------------------------------
// Final linear 32 -> 3 (+ squared norms)
// ---------------------------------------------------------------------------
__global__ void layer3_kernel(const float* __restrict__ W3, const float* __restrict__ b3, int n) {
    __shared__ float w[96], b[3];
    int tid = threadIdx.x;
    if (tid < 96) w[tid] = W3[tid];
    if (tid < 3) b[tid] = b3[tid];
    __syncthreads();
    int r = blockIdx.x * blockDim.x + tid;
    if (r >= n) return;
    const float* hv = g_hC + (size_t)r * 32;
    float o0 = b[0], o1 = b[1], o2 = b[2];
    #pragma unroll
    for (int k = 0; k < 32; k++) {
        float xv = hv[k];
        o0 = fmaf(xv, w[k], o0);
        o1 = fmaf(xv, w[32 + k], o1);
        o2 = fmaf(xv, w[64 + k], o2);
    }
    g_h3[3 * r] = o0; g_h3[3 * r + 1] = o1; g_h3[3 * r + 2] = o2;
    g_sq[r] = o0 * o0 + o1 * o1 + o2 * o2;
}

// ---------------------------------------------------------------------------
// Pairwise distances, reference-exact formula. 64x64 tile / block, 4x4 / thread
// ---------------------------------------------------------------------------
__global__ void pairwise_kernel(float* __restrict__ out, int n) {
    __shared__ float4 si[64], sj[64];
    int tid = threadIdx.x;
    int ib = blockIdx.y * 64, jb = blockIdx.x * 64;
    if (tid < 64) {
        int g = ib + tid;
        si[tid] = (g < n) ? make_float4(g_h3[3 * g], g_h3[3 * g + 1], g_h3[3 * g + 2], g_sq[g])
                          : make_float4(0.f, 0.f, 0.f, 0.f);
    } else if (tid < 128) {
        int t = tid - 64;
        int g = jb + t;
        sj[t] = (g < n) ? make_float4(g_h3[3 * g], g_h3[3 * g + 1], g_h3[3 * g + 2], g_sq[g])
                        : make_float4(0.f, 0.f, 0.f, 0.f);
    }
    __syncthreads();
    int tx = tid & 15, ty = tid >> 4;
    float4 a[4], b[4];
    #pragma unroll
    for (int i = 0; i < 4; i++) a[i] = si[ty * 4 + i];
    #pragma unroll
    for (int j = 0; j < 4; j++) b[j] = sj[tx * 4 + j];
    bool vec4ok = ((n & 3) == 0);
    #pragma unroll
    for (int i = 0; i < 4; i++) {
        int gr = ib + ty * 4 + i;
        if (gr >= n) continue;
        float res[4];
        #pragma unroll
        for (int j = 0; j < 4; j++) {
            float dot = a[i].x * b[j].x + a[i].y * b[j].y + a[i].z * b[j].z;
            float d2 = a[i].w + b[j].w - 2.f * dot;
            d2 = fmaxf(d2, 0.f);
            res[j] = (d2 > 0.f) ? sqrtf(d2) : 0.f;
        }
        int gc = jb + tx * 4;
        size_t o = (size_t)gr * n + gc;
        if (vec4ok && gc + 3 < n) {
            *(float4*)&out[o] = make_float4(res[0], res[1], res[2], res[3]);
        } else {
            for (int q = 0; q < 4; q++)
                if (gc + q < n) out[o + q] = res[q];
        }
    }
}

// ---------------------------------------------------------------------------
// Launch
// ---------------------------------------------------------------------------
extern "C" void kernel_launch(void* const* d_in, const int* in_sizes, int n_in,
                              void* d_out, int out_size) {
    const float* x      = (const float*)d_in[0];
    const int*   ei     = (const int*)  d_in[1];
    const float* W_gat  = (const float*)d_in[2];
    const float* b_gat  = (const float*)d_in[3];
    const float* attsrc = (const float*)d_in[4];
    const float* attdst = (const float*)d_in[5];
    const float* Wa     = (const float*)d_in[6];
    const float* ba     = (const float*)d_in[7];
    const float* lna_w  = (const float*)d_in[8];
    const float* lna_b  = (const float*)d_in[9];
    const float* W1     = (const float*)d_in[10];
    const float* b1     = (const float*)d_in[11];
    const float* ln1_w  = (const float*)d_in[12];
    const float* ln1_b  = (const float*)d_in[13];
    const float* W2     = (const float*)d_in[14];
    const float* b2     = (const float*)d_in[15];
    const float* ln2_w  = (const float*)d_in[16];
    const float* ln2_b  = (const float*)d_in[17];
    const float* W3     = (const float*)d_in[18];
    const float* b3     = (const float*)d_in[19];
    float* out = (float*)d_out;

    int n = in_sizes[0] / 256;
    int E = in_sizes[1] / 2;

    // edge sort by dst
    init_kernel<<<(n + 255) / 256, 256>>>(n);
    hist_kernel<<<(E + 255) / 256, 256>>>(ei, E);
    scan_kernel<<<1, 1024>>>(n);
    scatter_kernel<<<(E + 255) / 256, 256>>>(ei, E);

    // GAT linear transform: h = x @ W_gat^T   [n,256]
    gemm_gat_kernel<<<dim3(4, (n + 127) / 128), 256>>>(x, W_gat, n);

    // attention logits per node
    attn_kernel<<<(n + 7) / 8, 256>>>(attsrc, attdst, n);

    // softmax-weighted aggregation (+ bias + lrelu 0.01)
    gat_aggregate_kernel<<<n, 256>>>(b_gat, n);

    // MLP stack with fused LN + lrelu
    mlp_a_kernel<<<(n + 31) / 32, 256>>>(Wa, ba, lna_w, lna_b, n);
    mlp_1_kernel<<<(n + 63) / 64, 256>>>(W1, b1, ln1_w, ln1_b, n);
    mlp_2_kernel<<<(n + 127) / 128, 256>>>(W2, b2, ln2_w, ln2_b, n);

    // final projection + squared norms
    layer3_kernel<<<(n + 255) / 256, 256>>>(W3, b3, n);

    // pairwise distance matrix
    int gtiles = (n + 63) / 64;
    pairwise_kernel<<<dim3(gtiles, gtiles), 256>>>(out, n);
}